// round 7
// baseline (speedup 1.0000x reference)
#include <cuda_runtime.h>
#include <cuda_bf16.h>

#define N_NODES 50000
#define N_EDGES 800000
#define IN_DIM 128
#define HID_DIM 128
#define N_CLASSES 64

// ---------------- scratch: natively-typed __device__ globals ----------------
__device__ float4 g_hs1[N_NODES * 32];  // (x@W1)*dinv[row], 128 floats/row = 32 float4
__device__ float4 g_h1 [N_NODES * 32];  // relu(agg1)
__device__ float2 g_hs2[N_NODES * 32];  // (h1@W2)*dinv[row], 64 floats/row = 32 float2
__device__ int    g_counts[N_NODES];
__device__ int    g_cursor[N_NODES];
__device__ int    g_rowstart[N_NODES + 1];
__device__ int    g_blocksums[128];
__device__ int    g_csr[N_EDGES];
__device__ float  g_dinv[N_NODES];

// ---------------- CSR build ----------------
__global__ void k_init_counts() {
    int i = blockIdx.x * blockDim.x + threadIdx.x;
    if (i < N_NODES) { g_counts[i] = 0; g_cursor[i] = 0; }
}

// edge_index is int32 [2, N_EDGES]: row 0 = src, row 1 = dst
__global__ void k_hist(const int* __restrict__ dst) {
    int e = blockIdx.x * blockDim.x + threadIdx.x;
    if (e < N_EDGES) {
        int d = dst[e];
        if (d >= 0 && d < N_NODES) atomicAdd(&g_counts[d], 1);
    }
}

// 2-level exclusive scan of g_counts -> g_rowstart (512-thread blocks)
__global__ void k_scan_block() {
    __shared__ int s[512];
    int tid = threadIdx.x;
    int gid = blockIdx.x * 512 + tid;
    int v = (gid < N_NODES) ? g_counts[gid] : 0;
    s[tid] = v;
    __syncthreads();
    for (int off = 1; off < 512; off <<= 1) {
        int t = 0;
        if (tid >= off) t = s[tid - off];
        __syncthreads();
        if (tid >= off) s[tid] += t;
        __syncthreads();
    }
    if (gid < N_NODES) g_rowstart[gid] = s[tid] - v;  // exclusive
    if (tid == 511) g_blocksums[blockIdx.x] = s[511];
}

// parallel exclusive scan of <=128 block sums with ONE warp
__global__ void k_scan_sums(int nb) {
    int tid = threadIdx.x;     // 32 threads
    int per = (nb + 31) / 32;  // <= 4 for nb <= 128
    int loc[4];
    int lo = tid * per;
    int chunk = 0;
#pragma unroll
    for (int i = 0; i < 4; i++) {
        int idx = lo + i;
        int v = (i < per && idx < nb) ? g_blocksums[idx] : 0;
        loc[i] = chunk;        // exclusive-within-chunk prefix
        chunk += v;
    }
    int inc = chunk;           // inclusive scan of chunk totals
    for (int off = 1; off < 32; off <<= 1) {
        int t = __shfl_up_sync(0xffffffffu, inc, off);
        if (tid >= off) inc += t;
    }
    int excl = inc - chunk;    // exclusive prefix of this chunk
#pragma unroll
    for (int i = 0; i < 4; i++) {
        int idx = lo + i;
        if (i < per && idx < nb) g_blocksums[idx] = excl + loc[i];
    }
}

// adds block prefixes AND computes dinv (fused)
__global__ void k_scan_add() {
    int tid = threadIdx.x;
    int gid = blockIdx.x * 512 + tid;
    if (gid < N_NODES) {
        g_rowstart[gid] += g_blocksums[blockIdx.x];
        g_dinv[gid] = rsqrtf((float)(g_counts[gid] + 1));  // + self loop
    }
    if (blockIdx.x == 0 && tid == 0) g_rowstart[N_NODES] = N_EDGES;
}

__global__ void k_fill(const int* __restrict__ src, const int* __restrict__ dst) {
    int e = blockIdx.x * blockDim.x + threadIdx.x;
    if (e < N_EDGES) {
        int d = dst[e];
        int sv = src[e];
        if (d >= 0 && d < N_NODES && sv >= 0 && sv < N_NODES) {
            int pos = g_rowstart[d] + atomicAdd(&g_cursor[d], 1);
            if (pos >= 0 && pos < N_EDGES) g_csr[pos] = sv;
        }
    }
}

// ---------------- GEMM layer 1: g_hs1[r] = (x[r] @ W1) * dinv[r] ----------------
// Block = 64 rows x 128 cols, 256 threads. K-chunked KC=32.
// row_local = tid & 63 -> warp lanes share cg => Ws4 reads broadcast;
// Xs reads stride-33 -> conflict-free.
__global__ __launch_bounds__(256) void k_gemm1(const float* __restrict__ X,
                                               const float* __restrict__ W) {
    __shared__ float4 Ws4[32 * 32];     // 32 k-rows x 128 cols = 1024 float4
    __shared__ float  Xs[64][33];
    const int tid = threadIdx.x;
    const int row0 = blockIdx.x * 64;
    const int row_local = tid & 63;
    const int cg = tid >> 6;            // 0..3, 32 cols each

    float acc[32];
#pragma unroll
    for (int j = 0; j < 32; j++) acc[j] = 0.f;

    for (int kc0 = 0; kc0 < 128; kc0 += 32) {
        for (int i = tid; i < 1024; i += 256)
            Ws4[i] = ((const float4*)(W + kc0 * 128))[i];
        for (int i = tid; i < 512; i += 256) {
            int r = i >> 3, q = i & 7;
            int gr = row0 + r;
            float4 v = make_float4(0.f, 0.f, 0.f, 0.f);
            if (gr < N_NODES) v = ((const float4*)(X + gr * 128 + kc0))[q];
            Xs[r][q * 4 + 0] = v.x; Xs[r][q * 4 + 1] = v.y;
            Xs[r][q * 4 + 2] = v.z; Xs[r][q * 4 + 3] = v.w;
        }
        __syncthreads();

#pragma unroll 4
        for (int kk = 0; kk < 32; kk++) {
            float xv = Xs[row_local][kk];
            int base = kk * 32 + cg * 8;
#pragma unroll
            for (int j = 0; j < 8; j++) {
                float4 w = Ws4[base + j];
                acc[4 * j + 0] += xv * w.x;
                acc[4 * j + 1] += xv * w.y;
                acc[4 * j + 2] += xv * w.z;
                acc[4 * j + 3] += xv * w.w;
            }
        }
        __syncthreads();
    }

    int gr = row0 + row_local;
    if (gr < N_NODES) {
        float d = g_dinv[gr];
#pragma unroll
        for (int j = 0; j < 8; j++)
            g_hs1[gr * 32 + cg * 8 + j] =
                make_float4(acc[4 * j] * d, acc[4 * j + 1] * d,
                            acc[4 * j + 2] * d, acc[4 * j + 3] * d);
    }
}

// ---------------- GEMM layer 2: g_hs2[r] = (g_h1[r] @ W2) * dinv[r] ----------------
__global__ __launch_bounds__(256) void k_gemm2(const float* __restrict__ W) {
    __shared__ float4 Ws4[32 * 16];     // 32 k-rows x 64 cols = 512 float4
    __shared__ float  Xs[64][33];
    const int tid = threadIdx.x;
    const int row0 = blockIdx.x * 64;
    const int row_local = tid & 63;
    const int cg = tid >> 6;            // 0..3, 16 cols each

    float acc[16];
#pragma unroll
    for (int j = 0; j < 16; j++) acc[j] = 0.f;

    for (int kc0 = 0; kc0 < 128; kc0 += 32) {
        for (int i = tid; i < 512; i += 256)
            Ws4[i] = ((const float4*)(W + kc0 * 64))[i];
        for (int i = tid; i < 512; i += 256) {
            int r = i >> 3, q = i & 7;
            int gr = row0 + r;
            float4 v = make_float4(0.f, 0.f, 0.f, 0.f);
            if (gr < N_NODES) v = g_h1[gr * 32 + (kc0 >> 2) + q];
            Xs[r][q * 4 + 0] = v.x; Xs[r][q * 4 + 1] = v.y;
            Xs[r][q * 4 + 2] = v.z; Xs[r][q * 4 + 3] = v.w;
        }
        __syncthreads();

#pragma unroll 4
        for (int kk = 0; kk < 32; kk++) {
            float xv = Xs[row_local][kk];
            int base = kk * 16 + cg * 4;
#pragma unroll
            for (int j = 0; j < 4; j++) {
                float4 w = Ws4[base + j];
                acc[4 * j + 0] += xv * w.x;
                acc[4 * j + 1] += xv * w.y;
                acc[4 * j + 2] += xv * w.z;
                acc[4 * j + 3] += xv * w.w;
            }
        }
        __syncthreads();
    }

    int gr = row0 + row_local;
    if (gr < N_NODES) {
        float d = g_dinv[gr];
#pragma unroll
        for (int j = 0; j < 8; j++)
            g_hs2[gr * 32 + cg * 8 + j] =
                make_float2(acc[2 * j] * d, acc[2 * j + 1] * d);
    }
}

// ---------------- aggregation layer 1: warp per node, dual accumulators ----------------
// g_h1[node] = relu( (g_hs1[node] + sum_src g_hs1[src]) * dinv[node] + b1 )
__global__ __launch_bounds__(256) void k_agg1(const float* __restrict__ bias) {
    __shared__ int sidx[8][32];
    int node = (blockIdx.x * blockDim.x + threadIdx.x) >> 5;
    if (node >= N_NODES) return;
    int w = threadIdx.x >> 5;
    int lane = threadIdx.x & 31;

    int s = g_rowstart[node];
    int e = g_rowstart[node + 1];
    float d = g_dinv[node];

    float4 a = g_hs1[node * 32 + lane];  // self loop
    float4 a1 = make_float4(0.f, 0.f, 0.f, 0.f);
    for (int base = s; base < e; base += 32) {
        int idx = base + lane;
        sidx[w][lane] = (idx < e) ? g_csr[idx] : 0;
        __syncwarp();
        int cnt = min(32, e - base);
        int j = 0;
        for (; j + 1 < cnt; j += 2) {
            float4 v0 = g_hs1[sidx[w][j] * 32 + lane];
            float4 v1 = g_hs1[sidx[w][j + 1] * 32 + lane];
            a.x += v0.x; a.y += v0.y; a.z += v0.z; a.w += v0.w;
            a1.x += v1.x; a1.y += v1.y; a1.z += v1.z; a1.w += v1.w;
        }
        if (j < cnt) {
            float4 v = g_hs1[sidx[w][j] * 32 + lane];
            a.x += v.x; a.y += v.y; a.z += v.z; a.w += v.w;
        }
        __syncwarp();
    }
    a.x += a1.x; a.y += a1.y; a.z += a1.z; a.w += a1.w;
    float bx = bias[lane * 4 + 0], by = bias[lane * 4 + 1];
    float bz = bias[lane * 4 + 2], bw = bias[lane * 4 + 3];
    g_h1[node * 32 + lane] = make_float4(
        fmaxf(a.x * d + bx, 0.f), fmaxf(a.y * d + by, 0.f),
        fmaxf(a.z * d + bz, 0.f), fmaxf(a.w * d + bw, 0.f));
}

// ---------------- aggregation layer 2: writes harness output ----------------
__global__ __launch_bounds__(256) void k_agg2(const float* __restrict__ bias,
                                              float* __restrict__ out) {
    __shared__ int sidx[8][32];
    int node = (blockIdx.x * blockDim.x + threadIdx.x) >> 5;
    if (node >= N_NODES) return;
    int w = threadIdx.x >> 5;
    int lane = threadIdx.x & 31;

    int s = g_rowstart[node];
    int e = g_rowstart[node + 1];
    float d = g_dinv[node];

    float2 a = g_hs2[node * 32 + lane];  // self loop
    float2 a1 = make_float2(0.f, 0.f);
    for (int base = s; base < e; base += 32) {
        int idx = base + lane;
        sidx[w][lane] = (idx < e) ? g_csr[idx] : 0;
        __syncwarp();
        int cnt = min(32, e - base);
        int j = 0;
        for (; j + 1 < cnt; j += 2) {
            float2 v0 = g_hs2[sidx[w][j] * 32 + lane];
            float2 v1 = g_hs2[sidx[w][j + 1] * 32 + lane];
            a.x += v0.x; a.y += v0.y;
            a1.x += v1.x; a1.y += v1.y;
        }
        if (j < cnt) {
            float2 v = g_hs2[sidx[w][j] * 32 + lane];
            a.x += v.x; a.y += v.y;
        }
        __syncwarp();
    }
    a.x += a1.x; a.y += a1.y;
    float bx = bias[lane * 2 + 0], by = bias[lane * 2 + 1];
    out[node * 64 + lane * 2 + 0] = a.x * d + bx;
    out[node * 64 + lane * 2 + 1] = a.y * d + by;
}

// ---------------- launch: kernel launches ONLY ----------------
extern "C" void kernel_launch(void* const* d_in, const int* in_sizes, int n_in,
                              void* d_out, int out_size) {
    const float* x = (const float*)d_in[0];
    const int* ei = (const int*)d_in[1];   // int32 [2, N_EDGES]
    const float* W1 = (const float*)d_in[2];
    const float* b1 = (const float*)d_in[3];
    const float* W2 = (const float*)d_in[4];
    const float* b2 = (const float*)d_in[5];
    float* out = (float*)d_out;

    const int* esrc = ei;
    const int* edst = ei + N_EDGES;

    const int NB_SCAN = (N_NODES + 511) / 512;  // 98

    // CSR build + degrees
    k_init_counts<<<(N_NODES + 255) / 256, 256>>>();
    k_hist<<<(N_EDGES + 255) / 256, 256>>>(edst);
    k_scan_block<<<NB_SCAN, 512>>>();
    k_scan_sums<<<1, 32>>>(NB_SCAN);
    k_scan_add<<<NB_SCAN, 512>>>();   // also computes dinv
    k_fill<<<(N_EDGES + 255) / 256, 256>>>(esrc, edst);

    const int gemm_blocks = (N_NODES + 63) / 64;        // 782
    const int agg_blocks = (N_NODES + 7) / 8;           // 6250 (8 warps/block)

    // layer 1
    k_gemm1<<<gemm_blocks, 256>>>(x, W1);
    k_agg1<<<agg_blocks, 256>>>(b1);
    // layer 2
    k_gemm2<<<gemm_blocks, 256>>>(W2);
    k_agg2<<<agg_blocks, 256>>>(b2, out);
}

// round 8
// speedup vs baseline: 1.0810x; 1.0810x over previous
#include <cuda_runtime.h>
#include <cuda_fp16.h>

#define N_NODES 50000
#define N_EDGES 800000
#define IN_DIM 128
#define HID_DIM 128
#define N_CLASSES 64

// 8-byte packed vector of 4 halves
struct __align__(8) h4 { __half2 a, b; };

// ---------------- scratch: natively-typed __device__ globals ----------------
__device__ h4      g_hs1[N_NODES * 32];  // (x@W1)*dinv[row], 128 halves/row = 32 h4
__device__ h4      g_h1 [N_NODES * 32];  // relu(agg1), fp16
__device__ __half2 g_hs2[N_NODES * 32];  // (h1@W2)*dinv[row], 64 halves/row = 32 half2
__device__ int     g_counts[N_NODES];
__device__ int     g_cursor[N_NODES];
__device__ int     g_rowstart[N_NODES + 1];
__device__ int     g_blocksums[128];
__device__ int     g_csr[N_EDGES];
__device__ float   g_dinv[N_NODES];

// ---------------- CSR build ----------------
__global__ void k_init_counts() {
    int i = blockIdx.x * blockDim.x + threadIdx.x;
    if (i < N_NODES) { g_counts[i] = 0; g_cursor[i] = 0; }
}

// edge_index is int32 [2, N_EDGES]: row 0 = src, row 1 = dst
__global__ void k_hist(const int* __restrict__ dst) {
    int e = blockIdx.x * blockDim.x + threadIdx.x;
    if (e < N_EDGES) {
        int d = dst[e];
        if (d >= 0 && d < N_NODES) atomicAdd(&g_counts[d], 1);
    }
}

// 2-level exclusive scan of g_counts -> g_rowstart (512-thread blocks)
__global__ void k_scan_block() {
    __shared__ int s[512];
    int tid = threadIdx.x;
    int gid = blockIdx.x * 512 + tid;
    int v = (gid < N_NODES) ? g_counts[gid] : 0;
    s[tid] = v;
    __syncthreads();
    for (int off = 1; off < 512; off <<= 1) {
        int t = 0;
        if (tid >= off) t = s[tid - off];
        __syncthreads();
        if (tid >= off) s[tid] += t;
        __syncthreads();
    }
    if (gid < N_NODES) g_rowstart[gid] = s[tid] - v;  // exclusive
    if (tid == 511) g_blocksums[blockIdx.x] = s[511];
}

// parallel exclusive scan of <=128 block sums with ONE warp
__global__ void k_scan_sums(int nb) {
    int tid = threadIdx.x;     // 32 threads
    int per = (nb + 31) / 32;  // <= 4 for nb <= 128
    int loc[4];
    int lo = tid * per;
    int chunk = 0;
#pragma unroll
    for (int i = 0; i < 4; i++) {
        int idx = lo + i;
        int v = (i < per && idx < nb) ? g_blocksums[idx] : 0;
        loc[i] = chunk;        // exclusive-within-chunk prefix
        chunk += v;
    }
    int inc = chunk;           // inclusive scan of chunk totals
    for (int off = 1; off < 32; off <<= 1) {
        int t = __shfl_up_sync(0xffffffffu, inc, off);
        if (tid >= off) inc += t;
    }
    int excl = inc - chunk;    // exclusive prefix of this chunk
#pragma unroll
    for (int i = 0; i < 4; i++) {
        int idx = lo + i;
        if (i < per && idx < nb) g_blocksums[idx] = excl + loc[i];
    }
}

// adds block prefixes AND computes dinv (fused)
__global__ void k_scan_add() {
    int tid = threadIdx.x;
    int gid = blockIdx.x * 512 + tid;
    if (gid < N_NODES) {
        g_rowstart[gid] += g_blocksums[blockIdx.x];
        g_dinv[gid] = rsqrtf((float)(g_counts[gid] + 1));  // + self loop
    }
    if (blockIdx.x == 0 && tid == 0) g_rowstart[N_NODES] = N_EDGES;
}

__global__ void k_fill(const int* __restrict__ src, const int* __restrict__ dst) {
    int e = blockIdx.x * blockDim.x + threadIdx.x;
    if (e < N_EDGES) {
        int d = dst[e];
        int sv = src[e];
        if (d >= 0 && d < N_NODES && sv >= 0 && sv < N_NODES) {
            int pos = g_rowstart[d] + atomicAdd(&g_cursor[d], 1);
            if (pos >= 0 && pos < N_EDGES) g_csr[pos] = sv;
        }
    }
}

// ---------------- GEMM layer 1: g_hs1[r] = fp16( (x[r] @ W1) * dinv[r] ) ----------------
// Block = 64 rows x 128 cols, 256 threads. K-chunked KC=32. fp32 compute.
__global__ __launch_bounds__(256) void k_gemm1(const float* __restrict__ X,
                                               const float* __restrict__ W) {
    __shared__ float4 Ws4[32 * 32];     // 32 k-rows x 128 cols = 1024 float4
    __shared__ float  Xs[64][33];
    const int tid = threadIdx.x;
    const int row0 = blockIdx.x * 64;
    const int row_local = tid & 63;
    const int cg = tid >> 6;            // 0..3, 32 cols each

    float acc[32];
#pragma unroll
    for (int j = 0; j < 32; j++) acc[j] = 0.f;

    for (int kc0 = 0; kc0 < 128; kc0 += 32) {
        for (int i = tid; i < 1024; i += 256)
            Ws4[i] = ((const float4*)(W + kc0 * 128))[i];
        for (int i = tid; i < 512; i += 256) {
            int r = i >> 3, q = i & 7;
            int gr = row0 + r;
            float4 v = make_float4(0.f, 0.f, 0.f, 0.f);
            if (gr < N_NODES) v = ((const float4*)(X + gr * 128 + kc0))[q];
            Xs[r][q * 4 + 0] = v.x; Xs[r][q * 4 + 1] = v.y;
            Xs[r][q * 4 + 2] = v.z; Xs[r][q * 4 + 3] = v.w;
        }
        __syncthreads();

#pragma unroll 4
        for (int kk = 0; kk < 32; kk++) {
            float xv = Xs[row_local][kk];
            int base = kk * 32 + cg * 8;
#pragma unroll
            for (int j = 0; j < 8; j++) {
                float4 w = Ws4[base + j];
                acc[4 * j + 0] += xv * w.x;
                acc[4 * j + 1] += xv * w.y;
                acc[4 * j + 2] += xv * w.z;
                acc[4 * j + 3] += xv * w.w;
            }
        }
        __syncthreads();
    }

    int gr = row0 + row_local;
    if (gr < N_NODES) {
        float d = g_dinv[gr];
#pragma unroll
        for (int j = 0; j < 8; j++) {
            h4 h;
            h.a = __floats2half2_rn(acc[4 * j + 0] * d, acc[4 * j + 1] * d);
            h.b = __floats2half2_rn(acc[4 * j + 2] * d, acc[4 * j + 3] * d);
            g_hs1[gr * 32 + cg * 8 + j] = h;
        }
    }
}

// ---------------- GEMM layer 2: g_hs2[r] = fp16( (g_h1[r] @ W2) * dinv[r] ) ----------------
__global__ __launch_bounds__(256) void k_gemm2(const float* __restrict__ W) {
    __shared__ float4 Ws4[32 * 16];     // 32 k-rows x 64 cols = 512 float4
    __shared__ float  Xs[64][33];
    const int tid = threadIdx.x;
    const int row0 = blockIdx.x * 64;
    const int row_local = tid & 63;
    const int cg = tid >> 6;            // 0..3, 16 cols each

    float acc[16];
#pragma unroll
    for (int j = 0; j < 16; j++) acc[j] = 0.f;

    for (int kc0 = 0; kc0 < 128; kc0 += 32) {
        for (int i = tid; i < 512; i += 256)
            Ws4[i] = ((const float4*)(W + kc0 * 64))[i];
        for (int i = tid; i < 512; i += 256) {
            int r = i >> 3, q = i & 7;   // q-th h4 of the 32-wide chunk
            int gr = row0 + r;
            float2 lo = make_float2(0.f, 0.f), hi = make_float2(0.f, 0.f);
            if (gr < N_NODES) {
                h4 v = g_h1[gr * 32 + (kc0 >> 2) + q];
                lo = __half22float2(v.a);
                hi = __half22float2(v.b);
            }
            Xs[r][q * 4 + 0] = lo.x; Xs[r][q * 4 + 1] = lo.y;
            Xs[r][q * 4 + 2] = hi.x; Xs[r][q * 4 + 3] = hi.y;
        }
        __syncthreads();

#pragma unroll 4
        for (int kk = 0; kk < 32; kk++) {
            float xv = Xs[row_local][kk];
            int base = kk * 16 + cg * 4;
#pragma unroll
            for (int j = 0; j < 4; j++) {
                float4 w = Ws4[base + j];
                acc[4 * j + 0] += xv * w.x;
                acc[4 * j + 1] += xv * w.y;
                acc[4 * j + 2] += xv * w.z;
                acc[4 * j + 3] += xv * w.w;
            }
        }
        __syncthreads();
    }

    int gr = row0 + row_local;
    if (gr < N_NODES) {
        float d = g_dinv[gr];
#pragma unroll
        for (int j = 0; j < 8; j++)
            g_hs2[gr * 32 + cg * 8 + j] =
                __floats2half2_rn(acc[2 * j] * d, acc[2 * j + 1] * d);
    }
}

// ---------------- aggregation layer 1: warp per node, fp16 gather, fp32 accum ----------------
// g_h1[node] = fp16( relu( (hs1[node] + sum_src hs1[src]) * dinv[node] + b1 ) )
__global__ __launch_bounds__(256) void k_agg1(const float* __restrict__ bias) {
    __shared__ int sidx[8][32];
    int node = (blockIdx.x * blockDim.x + threadIdx.x) >> 5;
    if (node >= N_NODES) return;
    int w = threadIdx.x >> 5;
    int lane = threadIdx.x & 31;

    int s = g_rowstart[node];
    int e = g_rowstart[node + 1];
    float d = g_dinv[node];

    // self loop
    h4 hv = g_hs1[node * 32 + lane];
    float2 p = __half22float2(hv.a), q = __half22float2(hv.b);
    float4 a = make_float4(p.x, p.y, q.x, q.y);
    float4 a1 = make_float4(0.f, 0.f, 0.f, 0.f);

    for (int base = s; base < e; base += 32) {
        int idx = base + lane;
        sidx[w][lane] = (idx < e) ? g_csr[idx] : 0;
        __syncwarp();
        int cnt = min(32, e - base);
        int j = 0;
        for (; j + 1 < cnt; j += 2) {
            h4 v0 = g_hs1[sidx[w][j] * 32 + lane];
            h4 v1 = g_hs1[sidx[w][j + 1] * 32 + lane];
            float2 p0 = __half22float2(v0.a), q0 = __half22float2(v0.b);
            float2 p1 = __half22float2(v1.a), q1 = __half22float2(v1.b);
            a.x += p0.x; a.y += p0.y; a.z += q0.x; a.w += q0.y;
            a1.x += p1.x; a1.y += p1.y; a1.z += q1.x; a1.w += q1.y;
        }
        if (j < cnt) {
            h4 v = g_hs1[sidx[w][j] * 32 + lane];
            float2 pv = __half22float2(v.a), qv = __half22float2(v.b);
            a.x += pv.x; a.y += pv.y; a.z += qv.x; a.w += qv.y;
        }
        __syncwarp();
    }
    a.x += a1.x; a.y += a1.y; a.z += a1.z; a.w += a1.w;
    float bx = bias[lane * 4 + 0], by = bias[lane * 4 + 1];
    float bz = bias[lane * 4 + 2], bw = bias[lane * 4 + 3];
    h4 o;
    o.a = __floats2half2_rn(fmaxf(a.x * d + bx, 0.f), fmaxf(a.y * d + by, 0.f));
    o.b = __floats2half2_rn(fmaxf(a.z * d + bz, 0.f), fmaxf(a.w * d + bw, 0.f));
    g_h1[node * 32 + lane] = o;
}

// ---------------- aggregation layer 2: fp16 gather, fp32 output to harness ----------------
__global__ __launch_bounds__(256) void k_agg2(const float* __restrict__ bias,
                                              float* __restrict__ out) {
    __shared__ int sidx[8][32];
    int node = (blockIdx.x * blockDim.x + threadIdx.x) >> 5;
    if (node >= N_NODES) return;
    int w = threadIdx.x >> 5;
    int lane = threadIdx.x & 31;

    int s = g_rowstart[node];
    int e = g_rowstart[node + 1];
    float d = g_dinv[node];

    float2 a = __half22float2(g_hs2[node * 32 + lane]);  // self loop
    float2 a1 = make_float2(0.f, 0.f);
    for (int base = s; base < e; base += 32) {
        int idx = base + lane;
        sidx[w][lane] = (idx < e) ? g_csr[idx] : 0;
        __syncwarp();
        int cnt = min(32, e - base);
        int j = 0;
        for (; j + 1 < cnt; j += 2) {
            float2 v0 = __half22float2(g_hs2[sidx[w][j] * 32 + lane]);
            float2 v1 = __half22float2(g_hs2[sidx[w][j + 1] * 32 + lane]);
            a.x += v0.x; a.y += v0.y;
            a1.x += v1.x; a1.y += v1.y;
        }
        if (j < cnt) {
            float2 v = __half22float2(g_hs2[sidx[w][j] * 32 + lane]);
            a.x += v.x; a.y += v.y;
        }
        __syncwarp();
    }
    a.x += a1.x; a.y += a1.y;
    float bx = bias[lane * 2 + 0], by = bias[lane * 2 + 1];
    out[node * 64 + lane * 2 + 0] = a.x * d + bx;
    out[node * 64 + lane * 2 + 1] = a.y * d + by;
}

// ---------------- launch: kernel launches ONLY ----------------
extern "C" void kernel_launch(void* const* d_in, const int* in_sizes, int n_in,
                              void* d_out, int out_size) {
    const float* x = (const float*)d_in[0];
    const int* ei = (const int*)d_in[1];   // int32 [2, N_EDGES]
    const float* W1 = (const float*)d_in[2];
    const float* b1 = (const float*)d_in[3];
    const float* W2 = (const float*)d_in[4];
    const float* b2 = (const float*)d_in[5];
    float* out = (float*)d_out;

    const int* esrc = ei;
    const int* edst = ei + N_EDGES;

    const int NB_SCAN = (N_NODES + 511) / 512;  // 98

    // CSR build + degrees
    k_init_counts<<<(N_NODES + 255) / 256, 256>>>();
    k_hist<<<(N_EDGES + 255) / 256, 256>>>(edst);
    k_scan_block<<<NB_SCAN, 512>>>();
    k_scan_sums<<<1, 32>>>(NB_SCAN);
    k_scan_add<<<NB_SCAN, 512>>>();   // also computes dinv
    k_fill<<<(N_EDGES + 255) / 256, 256>>>(esrc, edst);

    const int gemm_blocks = (N_NODES + 63) / 64;        // 782
    const int agg_blocks = (N_NODES + 7) / 8;           // 6250 (8 warps/block)

    // layer 1
    k_gemm1<<<gemm_blocks, 256>>>(x, W1);
    k_agg1<<<agg_blocks, 256>>>(b1);
    // layer 2
    k_gemm2<<<gemm_blocks, 256>>>(W2);
    k_agg2<<<agg_blocks, 256>>>(b2, out);
}

// round 9
// speedup vs baseline: 1.3978x; 1.2931x over previous
#include <cuda_runtime.h>
#include <cuda_fp16.h>
#include <mma.h>

using namespace nvcuda;

#define N_NODES 50000
#define N_EDGES 800000
#define IN_DIM 128
#define HID_DIM 128
#define N_CLASSES 64
#define PAD_ROWS 64

// 8-byte packed vector of 4 halves
struct __align__(8) h4 { __half2 a, b; };

// ---------------- scratch: natively-typed __device__ globals ----------------
// feature tables padded by PAD_ROWS so wmma fragment loads at the ragged tail
// stay in-bounds (padded rows are never written -> remain zero, and their C
// rows are discarded by the epilogue guard).
__device__ h4      g_xh [(N_NODES + PAD_ROWS) * 32];  // x in fp16
__device__ h4      g_hs1[(N_NODES + PAD_ROWS) * 32];  // (x@W1)*dinv[row], fp16
__device__ h4      g_h1 [(N_NODES + PAD_ROWS) * 32];  // relu(agg1), fp16
__device__ __half2 g_hs2[N_NODES * 32];               // (h1@W2)*dinv[row], fp16
__device__ h4      g_w1h[128 * 32];                   // W1 fp16 [128x128]
__device__ h4      g_w2h[128 * 16];                   // W2 fp16 [128x64]
__device__ int     g_counts[N_NODES];
__device__ int     g_cursor[N_NODES];
__device__ int     g_rowstart[N_NODES + 1];
__device__ int     g_blocksums[128];
__device__ int     g_csr[N_EDGES];
__device__ float   g_dinv[N_NODES];

// ---------------- fp32 -> fp16 converts (dst selected device-side) ----------------
__global__ void k_cvt_x(const float* __restrict__ src) {
    int i = blockIdx.x * blockDim.x + threadIdx.x;
    if (i < N_NODES * 32) {
        float4 v = ((const float4*)src)[i];
        h4 h;
        h.a = __floats2half2_rn(v.x, v.y);
        h.b = __floats2half2_rn(v.z, v.w);
        g_xh[i] = h;
    }
}

__global__ void k_cvt_w(const float* __restrict__ w1, const float* __restrict__ w2) {
    int i = blockIdx.x * blockDim.x + threadIdx.x;
    if (i < 128 * 32) {
        float4 v = ((const float4*)w1)[i];
        h4 h;
        h.a = __floats2half2_rn(v.x, v.y);
        h.b = __floats2half2_rn(v.z, v.w);
        g_w1h[i] = h;
    }
    if (i < 128 * 16) {
        float4 v = ((const float4*)w2)[i];
        h4 h;
        h.a = __floats2half2_rn(v.x, v.y);
        h.b = __floats2half2_rn(v.z, v.w);
        g_w2h[i] = h;
    }
}

// ---------------- CSR build ----------------
__global__ void k_init_counts() {
    int i = blockIdx.x * blockDim.x + threadIdx.x;
    if (i < N_NODES) { g_counts[i] = 0; g_cursor[i] = 0; }
}

// edge_index is int32 [2, N_EDGES]: row 0 = src, row 1 = dst
__global__ void k_hist(const int* __restrict__ dst) {
    int e = blockIdx.x * blockDim.x + threadIdx.x;
    if (e < N_EDGES) {
        int d = dst[e];
        if (d >= 0 && d < N_NODES) atomicAdd(&g_counts[d], 1);
    }
}

// 2-level exclusive scan of g_counts -> g_rowstart (512-thread blocks)
__global__ void k_scan_block() {
    __shared__ int s[512];
    int tid = threadIdx.x;
    int gid = blockIdx.x * 512 + tid;
    int v = (gid < N_NODES) ? g_counts[gid] : 0;
    s[tid] = v;
    __syncthreads();
    for (int off = 1; off < 512; off <<= 1) {
        int t = 0;
        if (tid >= off) t = s[tid - off];
        __syncthreads();
        if (tid >= off) s[tid] += t;
        __syncthreads();
    }
    if (gid < N_NODES) g_rowstart[gid] = s[tid] - v;  // exclusive
    if (tid == 511) g_blocksums[blockIdx.x] = s[511];
}

// parallel exclusive scan of <=128 block sums with ONE warp
__global__ void k_scan_sums(int nb) {
    int tid = threadIdx.x;     // 32 threads
    int per = (nb + 31) / 32;  // <= 4 for nb <= 128
    int loc[4];
    int lo = tid * per;
    int chunk = 0;
#pragma unroll
    for (int i = 0; i < 4; i++) {
        int idx = lo + i;
        int v = (i < per && idx < nb) ? g_blocksums[idx] : 0;
        loc[i] = chunk;        // exclusive-within-chunk prefix
        chunk += v;
    }
    int inc = chunk;           // inclusive scan of chunk totals
    for (int off = 1; off < 32; off <<= 1) {
        int t = __shfl_up_sync(0xffffffffu, inc, off);
        if (tid >= off) inc += t;
    }
    int excl = inc - chunk;    // exclusive prefix of this chunk
#pragma unroll
    for (int i = 0; i < 4; i++) {
        int idx = lo + i;
        if (i < per && idx < nb) g_blocksums[idx] = excl + loc[i];
    }
}

// adds block prefixes AND computes dinv (fused)
__global__ void k_scan_add() {
    int tid = threadIdx.x;
    int gid = blockIdx.x * 512 + tid;
    if (gid < N_NODES) {
        g_rowstart[gid] += g_blocksums[blockIdx.x];
        g_dinv[gid] = rsqrtf((float)(g_counts[gid] + 1));  // + self loop
    }
    if (blockIdx.x == 0 && tid == 0) g_rowstart[N_NODES] = N_EDGES;
}

__global__ void k_fill(const int* __restrict__ src, const int* __restrict__ dst) {
    int e = blockIdx.x * blockDim.x + threadIdx.x;
    if (e < N_EDGES) {
        int d = dst[e];
        int sv = src[e];
        if (d >= 0 && d < N_NODES && sv >= 0 && sv < N_NODES) {
            int pos = g_rowstart[d] + atomicAdd(&g_cursor[d], 1);
            if (pos >= 0 && pos < N_EDGES) g_csr[pos] = sv;
        }
    }
}

// ---------------- GEMM layer 1 (tensor cores): g_hs1[r] = fp16( (x[r]@W1)*dinv[r] ) ----------------
// Block = 64 rows x 128 cols, 8 warps. Warp (mi=wid>>2, nj=wid&3) computes a
// 32x32 patch as 2x2 wmma 16x16x16 fragments, fp32 accum. A,B loaded from global.
__global__ __launch_bounds__(256) void k_gemm1_tc() {
    __shared__ float Cs[64 * 128];  // 32KB
    const int tid = threadIdx.x;
    const int wid = tid >> 5;
    const int row0 = blockIdx.x * 64;
    const int mi = wid >> 2;        // 0..1
    const int nj = wid & 3;         // 0..3

    wmma::fragment<wmma::accumulator, 16, 16, 16, float> c[2][2];
#pragma unroll
    for (int i = 0; i < 2; i++)
#pragma unroll
        for (int j = 0; j < 2; j++) wmma::fill_fragment(c[i][j], 0.f);

    const __half* A = (const __half*)g_xh + (size_t)row0 * 128;
    const __half* B = (const __half*)g_w1h;

    for (int k = 0; k < 128; k += 16) {
        wmma::fragment<wmma::matrix_a, 16, 16, 16, __half, wmma::row_major> a[2];
        wmma::load_matrix_sync(a[0], A + (mi * 32 + 0) * 128 + k, 128);
        wmma::load_matrix_sync(a[1], A + (mi * 32 + 16) * 128 + k, 128);
        wmma::fragment<wmma::matrix_b, 16, 16, 16, __half, wmma::row_major> b[2];
        wmma::load_matrix_sync(b[0], B + k * 128 + nj * 32 + 0, 128);
        wmma::load_matrix_sync(b[1], B + k * 128 + nj * 32 + 16, 128);
#pragma unroll
        for (int i = 0; i < 2; i++)
#pragma unroll
            for (int j = 0; j < 2; j++)
                wmma::mma_sync(c[i][j], a[i], b[j], c[i][j]);
    }

#pragma unroll
    for (int i = 0; i < 2; i++)
#pragma unroll
        for (int j = 0; j < 2; j++)
            wmma::store_matrix_sync(Cs + (mi * 32 + i * 16) * 128 + nj * 32 + j * 16,
                                    c[i][j], 128, wmma::mem_row_major);
    __syncthreads();

    // epilogue: scale by dinv[row], pack fp16
    for (int i = tid; i < 64 * 32; i += 256) {
        int r = i >> 5, cc = i & 31;
        int gr = row0 + r;
        if (gr < N_NODES) {
            float d = g_dinv[gr];
            float4 v = *(const float4*)(Cs + r * 128 + cc * 4);
            h4 h;
            h.a = __floats2half2_rn(v.x * d, v.y * d);
            h.b = __floats2half2_rn(v.z * d, v.w * d);
            g_hs1[(size_t)gr * 32 + cc] = h;
        }
    }
}

// ---------------- GEMM layer 2 (tensor cores): g_hs2[r] = fp16( (g_h1[r]@W2)*dinv[r] ) ----------------
// Block = 64 rows x 64 cols, 8 warps. Warp (mi=wid>>1, nj2=wid&1) computes a
// 16x32 patch as 1x2 fragments.
__global__ __launch_bounds__(256) void k_gemm2_tc() {
    __shared__ float Cs[64 * 64];   // 16KB
    const int tid = threadIdx.x;
    const int wid = tid >> 5;
    const int row0 = blockIdx.x * 64;
    const int mi = wid >> 1;        // 0..3
    const int nj2 = wid & 1;        // 0..1

    wmma::fragment<wmma::accumulator, 16, 16, 16, float> c[2];
#pragma unroll
    for (int j = 0; j < 2; j++) wmma::fill_fragment(c[j], 0.f);

    const __half* A = (const __half*)g_h1 + (size_t)row0 * 128;
    const __half* B = (const __half*)g_w2h;

    for (int k = 0; k < 128; k += 16) {
        wmma::fragment<wmma::matrix_a, 16, 16, 16, __half, wmma::row_major> a;
        wmma::load_matrix_sync(a, A + mi * 16 * 128 + k, 128);
        wmma::fragment<wmma::matrix_b, 16, 16, 16, __half, wmma::row_major> b[2];
        wmma::load_matrix_sync(b[0], B + k * 64 + nj2 * 32 + 0, 64);
        wmma::load_matrix_sync(b[1], B + k * 64 + nj2 * 32 + 16, 64);
#pragma unroll
        for (int j = 0; j < 2; j++)
            wmma::mma_sync(c[j], a, b[j], c[j]);
    }

#pragma unroll
    for (int j = 0; j < 2; j++)
        wmma::store_matrix_sync(Cs + mi * 16 * 64 + nj2 * 32 + j * 16,
                                c[j], 64, wmma::mem_row_major);
    __syncthreads();

    for (int i = tid; i < 64 * 32; i += 256) {
        int r = i >> 5, cc = i & 31;
        int gr = row0 + r;
        if (gr < N_NODES) {
            float d = g_dinv[gr];
            float2 v = *(const float2*)(Cs + r * 64 + cc * 2);
            g_hs2[(size_t)gr * 32 + cc] = __floats2half2_rn(v.x * d, v.y * d);
        }
    }
}

// ---------------- aggregation layer 1: warp per node, fp16 gather, fp32 accum ----------------
// g_h1[node] = fp16( relu( (hs1[node] + sum_src hs1[src]) * dinv[node] + b1 ) )
__global__ __launch_bounds__(256) void k_agg1(const float* __restrict__ bias) {
    __shared__ int sidx[8][32];
    int node = (blockIdx.x * blockDim.x + threadIdx.x) >> 5;
    if (node >= N_NODES) return;
    int w = threadIdx.x >> 5;
    int lane = threadIdx.x & 31;

    int s = g_rowstart[node];
    int e = g_rowstart[node + 1];
    float d = g_dinv[node];

    // self loop
    h4 hv = g_hs1[node * 32 + lane];
    float2 p = __half22float2(hv.a), q = __half22float2(hv.b);
    float4 a = make_float4(p.x, p.y, q.x, q.y);
    float4 a1 = make_float4(0.f, 0.f, 0.f, 0.f);

    for (int base = s; base < e; base += 32) {
        int idx = base + lane;
        sidx[w][lane] = (idx < e) ? g_csr[idx] : 0;
        __syncwarp();
        int cnt = min(32, e - base);
        int j = 0;
        for (; j + 1 < cnt; j += 2) {
            h4 v0 = g_hs1[sidx[w][j] * 32 + lane];
            h4 v1 = g_hs1[sidx[w][j + 1] * 32 + lane];
            float2 p0 = __half22float2(v0.a), q0 = __half22float2(v0.b);
            float2 p1 = __half22float2(v1.a), q1 = __half22float2(v1.b);
            a.x += p0.x; a.y += p0.y; a.z += q0.x; a.w += q0.y;
            a1.x += p1.x; a1.y += p1.y; a1.z += q1.x; a1.w += q1.y;
        }
        if (j < cnt) {
            h4 v = g_hs1[sidx[w][j] * 32 + lane];
            float2 pv = __half22float2(v.a), qv = __half22float2(v.b);
            a.x += pv.x; a.y += pv.y; a.z += qv.x; a.w += qv.y;
        }
        __syncwarp();
    }
    a.x += a1.x; a.y += a1.y; a.z += a1.z; a.w += a1.w;
    float bx = bias[lane * 4 + 0], by = bias[lane * 4 + 1];
    float bz = bias[lane * 4 + 2], bw = bias[lane * 4 + 3];
    h4 o;
    o.a = __floats2half2_rn(fmaxf(a.x * d + bx, 0.f), fmaxf(a.y * d + by, 0.f));
    o.b = __floats2half2_rn(fmaxf(a.z * d + bz, 0.f), fmaxf(a.w * d + bw, 0.f));
    g_h1[node * 32 + lane] = o;
}

// ---------------- aggregation layer 2: fp16 gather, fp32 output to harness ----------------
__global__ __launch_bounds__(256) void k_agg2(const float* __restrict__ bias,
                                              float* __restrict__ out) {
    __shared__ int sidx[8][32];
    int node = (blockIdx.x * blockDim.x + threadIdx.x) >> 5;
    if (node >= N_NODES) return;
    int w = threadIdx.x >> 5;
    int lane = threadIdx.x & 31;

    int s = g_rowstart[node];
    int e = g_rowstart[node + 1];
    float d = g_dinv[node];

    float2 a = __half22float2(g_hs2[node * 32 + lane]);  // self loop
    float2 a1 = make_float2(0.f, 0.f);
    for (int base = s; base < e; base += 32) {
        int idx = base + lane;
        sidx[w][lane] = (idx < e) ? g_csr[idx] : 0;
        __syncwarp();
        int cnt = min(32, e - base);
        int j = 0;
        for (; j + 1 < cnt; j += 2) {
            float2 v0 = __half22float2(g_hs2[sidx[w][j] * 32 + lane]);
            float2 v1 = __half22float2(g_hs2[sidx[w][j + 1] * 32 + lane]);
            a.x += v0.x; a.y += v0.y;
            a1.x += v1.x; a1.y += v1.y;
        }
        if (j < cnt) {
            float2 v = __half22float2(g_hs2[sidx[w][j] * 32 + lane]);
            a.x += v.x; a.y += v.y;
        }
        __syncwarp();
    }
    a.x += a1.x; a.y += a1.y;
    float bx = bias[lane * 2 + 0], by = bias[lane * 2 + 1];
    out[node * 64 + lane * 2 + 0] = a.x * d + bx;
    out[node * 64 + lane * 2 + 1] = a.y * d + by;
}

// ---------------- launch: kernel launches ONLY ----------------
extern "C" void kernel_launch(void* const* d_in, const int* in_sizes, int n_in,
                              void* d_out, int out_size) {
    const float* x = (const float*)d_in[0];
    const int* ei = (const int*)d_in[1];   // int32 [2, N_EDGES]
    const float* W1 = (const float*)d_in[2];
    const float* b1 = (const float*)d_in[3];
    const float* W2 = (const float*)d_in[4];
    const float* b2 = (const float*)d_in[5];
    float* out = (float*)d_out;

    const int* esrc = ei;
    const int* edst = ei + N_EDGES;

    const int NB_SCAN = (N_NODES + 511) / 512;  // 98

    // fp16 conversions
    k_cvt_x<<<(N_NODES * 32 + 255) / 256, 256>>>(x);
    k_cvt_w<<<(128 * 32 + 255) / 256, 256>>>(W1, W2);

    // CSR build + degrees
    k_init_counts<<<(N_NODES + 255) / 256, 256>>>();
    k_hist<<<(N_EDGES + 255) / 256, 256>>>(edst);
    k_scan_block<<<NB_SCAN, 512>>>();
    k_scan_sums<<<1, 32>>>(NB_SCAN);
    k_scan_add<<<NB_SCAN, 512>>>();   // also computes dinv
    k_fill<<<(N_EDGES + 255) / 256, 256>>>(esrc, edst);

    const int gemm_blocks = (N_NODES + 63) / 64;        // 782
    const int agg_blocks = (N_NODES + 7) / 8;           // 6250 (8 warps/block)

    // layer 1
    k_gemm1_tc<<<gemm_blocks, 256>>>();
    k_agg1<<<agg_blocks, 256>>>(b1);
    // layer 2
    k_gemm2_tc<<<gemm_blocks, 256>>>();
    k_agg2<<<agg_blocks, 256>>>(b2, out);
}

// round 10
// speedup vs baseline: 1.5658x; 1.1202x over previous
#include <cuda_runtime.h>
#include <cuda_fp16.h>
#include <mma.h>

using namespace nvcuda;

#define N_NODES 50000
#define N_EDGES 800000
#define IN_DIM 128
#define HID_DIM 128
#define N_CLASSES 64
#define PAD_ROWS 64

// 8-byte packed vector of 4 halves
struct __align__(8) h4 { __half2 a, b; };

// ---------------- scratch: natively-typed __device__ globals ----------------
// feature tables padded by PAD_ROWS so wmma fragment loads at the ragged tail
// stay in-bounds (padded rows never written -> zero; their C rows discarded).
__device__ h4      g_hs1[(N_NODES + PAD_ROWS) * 32];  // (x@W1)*dinv[row], fp16
__device__ h4      g_h1 [(N_NODES + PAD_ROWS) * 32];  // relu(agg1), fp16
__device__ __half2 g_hs2[N_NODES * 32];               // (h1@W2)*dinv[row], fp16
__device__ h4      g_w1h[128 * 32];                   // W1 fp16 [128x128]
__device__ h4      g_w2h[128 * 16];                   // W2 fp16 [128x64]
__device__ int     g_counts[N_NODES];
__device__ int     g_rowstart[N_NODES];               // after fill: rs[n] = orig_rs[n+1]
__device__ int     g_blocksums[128];
__device__ int     g_csr[N_EDGES];
__device__ float   g_dinv[N_NODES];

// ---------------- prep: convert W1/W2 to fp16, zero counts (one launch) ----------------
__global__ void k_prep(const float* __restrict__ w1, const float* __restrict__ w2) {
    int i = blockIdx.x * blockDim.x + threadIdx.x;
    if (i < 128 * 32) {
        float4 v = ((const float4*)w1)[i];
        h4 h;
        h.a = __floats2half2_rn(v.x, v.y);
        h.b = __floats2half2_rn(v.z, v.w);
        g_w1h[i] = h;
    }
    if (i < 128 * 16) {
        float4 v = ((const float4*)w2)[i];
        h4 h;
        h.a = __floats2half2_rn(v.x, v.y);
        h.b = __floats2half2_rn(v.z, v.w);
        g_w2h[i] = h;
    }
    if (i < N_NODES) g_counts[i] = 0;
}

// ---------------- CSR build ----------------
// edge_index is int32 [2, N_EDGES]: row 0 = src, row 1 = dst
__global__ void k_hist(const int* __restrict__ dst) {
    int e = blockIdx.x * blockDim.x + threadIdx.x;
    if (e < N_EDGES) {
        int d = dst[e];
        if (d >= 0 && d < N_NODES) atomicAdd(&g_counts[d], 1);
    }
}

// per-512-block exclusive scan; block totals to g_blocksums
__global__ void k_scan_block() {
    __shared__ int s[512];
    int tid = threadIdx.x;
    int gid = blockIdx.x * 512 + tid;
    int v = (gid < N_NODES) ? g_counts[gid] : 0;
    s[tid] = v;
    __syncthreads();
    for (int off = 1; off < 512; off <<= 1) {
        int t = 0;
        if (tid >= off) t = s[tid - off];
        __syncthreads();
        if (tid >= off) s[tid] += t;
        __syncthreads();
    }
    if (gid < N_NODES) g_rowstart[gid] = s[tid] - v;  // exclusive within block
    if (tid == 511) g_blocksums[blockIdx.x] = s[511];
}

// each block self-computes its prefix over blocksums[0..bid), adds it,
// and computes dinv (fused). No separate scan_sums launch.
__global__ void k_scan_add() {
    __shared__ int sprefix;
    int tid = threadIdx.x;
    int bid = blockIdx.x;
    if (tid < 32) {
        int acc = 0;
        for (int i = tid; i < bid; i += 32) acc += g_blocksums[i];
#pragma unroll
        for (int off = 16; off > 0; off >>= 1)
            acc += __shfl_down_sync(0xffffffffu, acc, off);
        if (tid == 0) sprefix = acc;
    }
    __syncthreads();
    int gid = bid * 512 + tid;
    if (gid < N_NODES) {
        g_rowstart[gid] += sprefix;
        g_dinv[gid] = rsqrtf((float)(g_counts[gid] + 1));  // + self loop
    }
}

// fill bumps rowstart directly: after this, rowstart[n] = orig_rowstart[n+1]
__global__ void k_fill(const int* __restrict__ src, const int* __restrict__ dst) {
    int e = blockIdx.x * blockDim.x + threadIdx.x;
    if (e < N_EDGES) {
        int d = dst[e];
        int sv = src[e];
        if (d >= 0 && d < N_NODES && sv >= 0 && sv < N_NODES) {
            int pos = atomicAdd(&g_rowstart[d], 1);
            if (pos >= 0 && pos < N_EDGES) g_csr[pos] = sv;
        }
    }
}

// ---------------- GEMM layer 1 (tensor cores, fp32 X staged to fp16 smem) ----------------
// g_hs1[r] = fp16( (x[r]@W1)*dinv[r] ). Block = 64 rows x 128 cols, 8 warps.
// Warp (mi=wid>>2, nj=wid&3) computes a 32x32 patch as 2x2 wmma fragments.
// smem union: A-tile (fp16, stride 136) during mainloop, Cs (fp32) in epilogue.
__global__ __launch_bounds__(256) void k_gemm1_tc(const float* __restrict__ X) {
    __shared__ union SM1 {
        __half a[64 * 136];   // 17.4KB, row stride 136 halves = 272B (16B-mult)
        float  c[64 * 128];   // 32KB
    } sm;
    const int tid = threadIdx.x;
    const int wid = tid >> 5;
    const int row0 = blockIdx.x * 64;
    const int mi = wid >> 2;        // 0..1
    const int nj = wid & 3;         // 0..3

    // stage X tile: fp32 global -> fp16 smem (zeros past N_NODES)
    for (int i = tid; i < 64 * 32; i += 256) {
        int r = i >> 5, q = i & 31;
        int gr = row0 + r;
        float4 v = make_float4(0.f, 0.f, 0.f, 0.f);
        if (gr < N_NODES) v = ((const float4*)(X + (size_t)gr * 128))[q];
        __half2* dst = (__half2*)(sm.a + r * 136 + q * 4);
        dst[0] = __floats2half2_rn(v.x, v.y);
        dst[1] = __floats2half2_rn(v.z, v.w);
    }
    __syncthreads();

    wmma::fragment<wmma::accumulator, 16, 16, 16, float> c[2][2];
#pragma unroll
    for (int i = 0; i < 2; i++)
#pragma unroll
        for (int j = 0; j < 2; j++) wmma::fill_fragment(c[i][j], 0.f);

    const __half* B = (const __half*)g_w1h;

    for (int k = 0; k < 128; k += 16) {
        wmma::fragment<wmma::matrix_a, 16, 16, 16, __half, wmma::row_major> a[2];
        wmma::load_matrix_sync(a[0], sm.a + (mi * 32 + 0) * 136 + k, 136);
        wmma::load_matrix_sync(a[1], sm.a + (mi * 32 + 16) * 136 + k, 136);
        wmma::fragment<wmma::matrix_b, 16, 16, 16, __half, wmma::row_major> b[2];
        wmma::load_matrix_sync(b[0], B + k * 128 + nj * 32 + 0, 128);
        wmma::load_matrix_sync(b[1], B + k * 128 + nj * 32 + 16, 128);
#pragma unroll
        for (int i = 0; i < 2; i++)
#pragma unroll
            for (int j = 0; j < 2; j++)
                wmma::mma_sync(c[i][j], a[i], b[j], c[i][j]);
    }
    __syncthreads();   // all warps done reading sm.a before aliasing as sm.c

#pragma unroll
    for (int i = 0; i < 2; i++)
#pragma unroll
        for (int j = 0; j < 2; j++)
            wmma::store_matrix_sync(sm.c + (mi * 32 + i * 16) * 128 + nj * 32 + j * 16,
                                    c[i][j], 128, wmma::mem_row_major);
    __syncthreads();

    // epilogue: scale by dinv[row], pack fp16
    for (int i = tid; i < 64 * 32; i += 256) {
        int r = i >> 5, cc = i & 31;
        int gr = row0 + r;
        if (gr < N_NODES) {
            float d = g_dinv[gr];
            float4 v = *(const float4*)(sm.c + r * 128 + cc * 4);
            h4 h;
            h.a = __floats2half2_rn(v.x * d, v.y * d);
            h.b = __floats2half2_rn(v.z * d, v.w * d);
            g_hs1[(size_t)gr * 32 + cc] = h;
        }
    }
}

// ---------------- GEMM layer 2 (tensor cores): g_hs2[r] = fp16( (g_h1[r]@W2)*dinv[r] ) ----------------
__global__ __launch_bounds__(256) void k_gemm2_tc() {
    __shared__ float Cs[64 * 64];   // 16KB
    const int tid = threadIdx.x;
    const int wid = tid >> 5;
    const int row0 = blockIdx.x * 64;
    const int mi = wid >> 1;        // 0..3
    const int nj2 = wid & 1;        // 0..1

    wmma::fragment<wmma::accumulator, 16, 16, 16, float> c[2];
#pragma unroll
    for (int j = 0; j < 2; j++) wmma::fill_fragment(c[j], 0.f);

    const __half* A = (const __half*)g_h1 + (size_t)row0 * 128;
    const __half* B = (const __half*)g_w2h;

    for (int k = 0; k < 128; k += 16) {
        wmma::fragment<wmma::matrix_a, 16, 16, 16, __half, wmma::row_major> a;
        wmma::load_matrix_sync(a, A + mi * 16 * 128 + k, 128);
        wmma::fragment<wmma::matrix_b, 16, 16, 16, __half, wmma::row_major> b[2];
        wmma::load_matrix_sync(b[0], B + k * 64 + nj2 * 32 + 0, 64);
        wmma::load_matrix_sync(b[1], B + k * 64 + nj2 * 32 + 16, 64);
#pragma unroll
        for (int j = 0; j < 2; j++)
            wmma::mma_sync(c[j], a, b[j], c[j]);
    }

#pragma unroll
    for (int j = 0; j < 2; j++)
        wmma::store_matrix_sync(Cs + mi * 16 * 64 + nj2 * 32 + j * 16,
                                c[j], 64, wmma::mem_row_major);
    __syncthreads();

    for (int i = tid; i < 64 * 32; i += 256) {
        int r = i >> 5, cc = i & 31;
        int gr = row0 + r;
        if (gr < N_NODES) {
            float d = g_dinv[gr];
            float2 v = *(const float2*)(Cs + r * 64 + cc * 2);
            g_hs2[(size_t)gr * 32 + cc] = __floats2half2_rn(v.x * d, v.y * d);
        }
    }
}

// ---------------- aggregation layer 1: warp per node, fp16 gather, fp32 accum ----------------
// CSR range after fill-bump: s = node? rs[node-1] : 0, e = rs[node]
__global__ __launch_bounds__(256) void k_agg1(const float* __restrict__ bias) {
    __shared__ int sidx[8][32];
    int node = (blockIdx.x * blockDim.x + threadIdx.x) >> 5;
    if (node >= N_NODES) return;
    int w = threadIdx.x >> 5;
    int lane = threadIdx.x & 31;

    int s = node ? g_rowstart[node - 1] : 0;
    int e = g_rowstart[node];
    float d = g_dinv[node];

    // self loop
    h4 hv = g_hs1[node * 32 + lane];
    float2 p = __half22float2(hv.a), q = __half22float2(hv.b);
    float4 a = make_float4(p.x, p.y, q.x, q.y);
    float4 a1 = make_float4(0.f, 0.f, 0.f, 0.f);

    for (int base = s; base < e; base += 32) {
        int idx = base + lane;
        sidx[w][lane] = (idx < e) ? g_csr[idx] : 0;
        __syncwarp();
        int cnt = min(32, e - base);
        int j = 0;
        for (; j + 1 < cnt; j += 2) {
            h4 v0 = g_hs1[sidx[w][j] * 32 + lane];
            h4 v1 = g_hs1[sidx[w][j + 1] * 32 + lane];
            float2 p0 = __half22float2(v0.a), q0 = __half22float2(v0.b);
            float2 p1 = __half22float2(v1.a), q1 = __half22float2(v1.b);
            a.x += p0.x; a.y += p0.y; a.z += q0.x; a.w += q0.y;
            a1.x += p1.x; a1.y += p1.y; a1.z += q1.x; a1.w += q1.y;
        }
        if (j < cnt) {
            h4 v = g_hs1[sidx[w][j] * 32 + lane];
            float2 pv = __half22float2(v.a), qv = __half22float2(v.b);
            a.x += pv.x; a.y += pv.y; a.z += qv.x; a.w += qv.y;
        }
        __syncwarp();
    }
    a.x += a1.x; a.y += a1.y; a.z += a1.z; a.w += a1.w;
    float bx = bias[lane * 4 + 0], by = bias[lane * 4 + 1];
    float bz = bias[lane * 4 + 2], bw = bias[lane * 4 + 3];
    h4 o;
    o.a = __floats2half2_rn(fmaxf(a.x * d + bx, 0.f), fmaxf(a.y * d + by, 0.f));
    o.b = __floats2half2_rn(fmaxf(a.z * d + bz, 0.f), fmaxf(a.w * d + bw, 0.f));
    g_h1[node * 32 + lane] = o;
}

// ---------------- aggregation layer 2: fp16 gather, fp32 output to harness ----------------
__global__ __launch_bounds__(256) void k_agg2(const float* __restrict__ bias,
                                              float* __restrict__ out) {
    __shared__ int sidx[8][32];
    int node = (blockIdx.x * blockDim.x + threadIdx.x) >> 5;
    if (node >= N_NODES) return;
    int w = threadIdx.x >> 5;
    int lane = threadIdx.x & 31;

    int s = node ? g_rowstart[node - 1] : 0;
    int e = g_rowstart[node];
    float d = g_dinv[node];

    float2 a = __half22float2(g_hs2[node * 32 + lane]);  // self loop
    float2 a1 = make_float2(0.f, 0.f);
    for (int base = s; base < e; base += 32) {
        int idx = base + lane;
        sidx[w][lane] = (idx < e) ? g_csr[idx] : 0;
        __syncwarp();
        int cnt = min(32, e - base);
        int j = 0;
        for (; j + 1 < cnt; j += 2) {
            float2 v0 = __half22float2(g_hs2[sidx[w][j] * 32 + lane]);
            float2 v1 = __half22float2(g_hs2[sidx[w][j + 1] * 32 + lane]);
            a.x += v0.x; a.y += v0.y;
            a1.x += v1.x; a1.y += v1.y;
        }
        if (j < cnt) {
            float2 v = __half22float2(g_hs2[sidx[w][j] * 32 + lane]);
            a.x += v.x; a.y += v.y;
        }
        __syncwarp();
    }
    a.x += a1.x; a.y += a1.y;
    float bx = bias[lane * 2 + 0], by = bias[lane * 2 + 1];
    out[node * 64 + lane * 2 + 0] = a.x * d + bx;
    out[node * 64 + lane * 2 + 1] = a.y * d + by;
}

// ---------------- launch: kernel launches ONLY (9 launches) ----------------
extern "C" void kernel_launch(void* const* d_in, const int* in_sizes, int n_in,
                              void* d_out, int out_size) {
    const float* x = (const float*)d_in[0];
    const int* ei = (const int*)d_in[1];   // int32 [2, N_EDGES]
    const float* W1 = (const float*)d_in[2];
    const float* b1 = (const float*)d_in[3];
    const float* W2 = (const float*)d_in[4];
    const float* b2 = (const float*)d_in[5];
    float* out = (float*)d_out;

    const int* esrc = ei;
    const int* edst = ei + N_EDGES;

    const int NB_SCAN = (N_NODES + 511) / 512;  // 98

    k_prep<<<(N_NODES + 255) / 256, 256>>>(W1, W2);
    k_hist<<<(N_EDGES + 255) / 256, 256>>>(edst);
    k_scan_block<<<NB_SCAN, 512>>>();
    k_scan_add<<<NB_SCAN, 512>>>();   // self-scans blocksums, computes dinv
    k_fill<<<(N_EDGES + 255) / 256, 256>>>(esrc, edst);

    const int gemm_blocks = (N_NODES + 63) / 64;        // 782
    const int agg_blocks = (N_NODES + 7) / 8;           // 6250 (8 warps/block)

    // layer 1
    k_gemm1_tc<<<gemm_blocks, 256>>>(x);
    k_agg1<<<agg_blocks, 256>>>(b1);
    // layer 2
    k_gemm2_tc<<<gemm_blocks, 256>>>();
    k_agg2<<<agg_blocks, 256>>>(b2, out);
}